// round 11
// baseline (speedup 1.0000x reference)
#include <cuda_runtime.h>
#include <cuda_fp16.h>
#include <cstdint>

// CosinePrediction: cos[e] = <u[src[e]], v[dst[e]]> / (||u||*||v||)
// Phase 1 (single fused launch): L2-normalize ALL rows of both tensors,
//   store fp16 rows (128 B/row) in scratch.
// Phase 2: PERSISTENT gather. 16 lanes per edge, uint2 (8B) loads:
//   same 1-wavefront-per-row efficiency, half the buffer registers of the
//   uint4 variant -> 6 blocks/SM occupancy with 8 loads in flight/thread.
//   R8 loop shape (index prefetch one iter ahead); no double buffering
//   (R9 showed per-thread MLP beats structural pipelining here).

static constexpr int D = 64;
static constexpr int MAX_ROWS = 100000;       // N_U = N_I = 100000 (fixed problem shape)
static constexpr int THREADS = 256;
static constexpr int GATHER_BLOCKS = 888;     // 6 blocks/SM * 148 SMs, persistent

// fp16 normalized rows (25.6 MB total scratch)
__device__ __half g_nu[(size_t)MAX_ROWS * D];
__device__ __half g_ni[(size_t)MAX_ROWS * D];

// ---------------- Phase 1: fused normalize + fp16 convert ----------------
__device__ __forceinline__ void norm_store(
    const float4 a, const float4 b, float rn, __half* __restrict__ drow, int lane)
{
    __half2 h[4];
    h[0] = __floats2half2_rn(a.x * rn, a.y * rn);
    h[1] = __floats2half2_rn(a.z * rn, a.w * rn);
    h[2] = __floats2half2_rn(b.x * rn, b.y * rn);
    h[3] = __floats2half2_rn(b.z * rn, b.w * rn);
    *reinterpret_cast<uint2*>(drow + 4 * lane)      = *reinterpret_cast<uint2*>(&h[0]);
    *reinterpret_cast<uint2*>(drow + 32 + 4 * lane) = *reinterpret_cast<uint2*>(&h[2]);
}

__global__ __launch_bounds__(THREADS) void normalize_fused_kernel(
    const float* __restrict__ h_user,
    const float* __restrict__ h_item,
    int n_user, int n_total)
{
    const int gid  = blockIdx.x * THREADS + threadIdx.x;
    const int p    = gid >> 3;           // row-pair index
    const int lane = gid & 7;
    const int r0   = p * 2;
    if (r0 >= n_total) return;
    const int r1 = r0 + 1;

    const float* src0 = (r0 < n_user) ? (h_user + (long long)r0 * D)
                                      : (h_item + (long long)(r0 - n_user) * D);
    __half* dst0 = (r0 < n_user) ? (g_nu + (long long)r0 * D)
                                 : (g_ni + (long long)(r0 - n_user) * D);

    const bool have1 = r1 < n_total;
    const float* src1 = src0;
    __half* dst1 = dst0;
    if (have1) {
        src1 = (r1 < n_user) ? (h_user + (long long)r1 * D)
                             : (h_item + (long long)(r1 - n_user) * D);
        dst1 = (r1 < n_user) ? (g_nu + (long long)r1 * D)
                             : (g_ni + (long long)(r1 - n_user) * D);
    }

    const float4 a0 = __ldg(reinterpret_cast<const float4*>(src0) + lane);
    const float4 b0 = __ldg(reinterpret_cast<const float4*>(src0) + lane + 8);
    const float4 a1 = __ldg(reinterpret_cast<const float4*>(src1) + lane);
    const float4 b1 = __ldg(reinterpret_cast<const float4*>(src1) + lane + 8);

    float n0 = a0.x * a0.x;
    n0 = fmaf(a0.y, a0.y, n0); n0 = fmaf(a0.z, a0.z, n0); n0 = fmaf(a0.w, a0.w, n0);
    n0 = fmaf(b0.x, b0.x, n0); n0 = fmaf(b0.y, b0.y, n0);
    n0 = fmaf(b0.z, b0.z, n0); n0 = fmaf(b0.w, b0.w, n0);

    float n1 = a1.x * a1.x;
    n1 = fmaf(a1.y, a1.y, n1); n1 = fmaf(a1.z, a1.z, n1); n1 = fmaf(a1.w, a1.w, n1);
    n1 = fmaf(b1.x, b1.x, n1); n1 = fmaf(b1.y, b1.y, n1);
    n1 = fmaf(b1.z, b1.z, n1); n1 = fmaf(b1.w, b1.w, n1);

    #pragma unroll
    for (int o = 4; o > 0; o >>= 1) {
        n0 += __shfl_xor_sync(0xFFFFFFFFu, n0, o);
        n1 += __shfl_xor_sync(0xFFFFFFFFu, n1, o);
    }

    norm_store(a0, b0, rsqrtf(n0), dst0, lane);
    if (have1) norm_store(a1, b1, rsqrtf(n1), dst1, lane);
}

// ---------------- Phase 2: persistent edge gather + dot ----------------
// 4 halves per lane: depth-2 fp16 accumulation (1 HMUL2 + 1 fused HFMA2),
// then one f32 convert pair. Same rounding profile as the R8 kernel.
__device__ __forceinline__ float dot4h(uint2 w, uint2 z)
{
    const __half2* wh = reinterpret_cast<const __half2*>(&w);
    const __half2* zh = reinterpret_cast<const __half2*>(&z);
    const __half2 p = __hfma2(wh[0], zh[0], __hmul2(wh[1], zh[1]));
    const float2 f = __half22float2(p);
    return f.x + f.y;
}

__global__ __launch_bounds__(THREADS, 6) void cosine_gather_kernel(
    const int* __restrict__ src_idx,
    const int* __restrict__ dst_idx,
    float* __restrict__ out,
    int E)
{
    const int gid     = blockIdx.x * THREADS + threadIdx.x;
    const int lane    = gid & 15;                          // lane within 16-lane group
    const int gstride = (GATHER_BLOCKS * THREADS) >> 4;    // quads per sweep
    const int nquads  = E >> 2;                            // full quads

    int g = gid >> 4;
    if (g < nquads) {
        // Prime the pipeline: indices for the first quad (broadcast int4).
        int4 s4 = __ldg(reinterpret_cast<const int4*>(src_idx) + g);
        int4 d4 = __ldg(reinterpret_cast<const int4*>(dst_idx) + g);

        while (true) {
            const int gn = g + gstride;

            // 8 independent 8B gathers — indices already resident.
            const uint2 w0 = __ldg(reinterpret_cast<const uint2*>(g_nu + (long long)s4.x * D) + lane);
            const uint2 z0 = __ldg(reinterpret_cast<const uint2*>(g_ni + (long long)d4.x * D) + lane);
            const uint2 w1 = __ldg(reinterpret_cast<const uint2*>(g_nu + (long long)s4.y * D) + lane);
            const uint2 z1 = __ldg(reinterpret_cast<const uint2*>(g_ni + (long long)d4.y * D) + lane);
            const uint2 w2 = __ldg(reinterpret_cast<const uint2*>(g_nu + (long long)s4.z * D) + lane);
            const uint2 z2 = __ldg(reinterpret_cast<const uint2*>(g_ni + (long long)d4.z * D) + lane);
            const uint2 w3 = __ldg(reinterpret_cast<const uint2*>(g_nu + (long long)s4.w * D) + lane);
            const uint2 z3 = __ldg(reinterpret_cast<const uint2*>(g_ni + (long long)d4.w * D) + lane);

            // Prefetch next quad's indices while rows are in flight.
            const bool more = gn < nquads;
            if (more) {
                s4 = __ldg(reinterpret_cast<const int4*>(src_idx) + gn);
                d4 = __ldg(reinterpret_cast<const int4*>(dst_idx) + gn);
            }

            float c0 = dot4h(w0, z0);
            float c1 = dot4h(w1, z1);
            float c2 = dot4h(w2, z2);
            float c3 = dot4h(w3, z3);

            #pragma unroll
            for (int o = 8; o > 0; o >>= 1) {
                c0 += __shfl_xor_sync(0xFFFFFFFFu, c0, o);
                c1 += __shfl_xor_sync(0xFFFFFFFFu, c1, o);
                c2 += __shfl_xor_sync(0xFFFFFFFFu, c2, o);
                c3 += __shfl_xor_sync(0xFFFFFFFFu, c3, o);
            }

            if (lane == 0) {
                float4 r; r.x = c0; r.y = c1; r.z = c2; r.w = c3;
                *reinterpret_cast<float4*>(out + g * 4) = r;   // single STG.128
            }

            if (!more) break;
            g = gn;
        }
    }

    // Tail edges (E % 4), handled by the first 16-lane group of block 0.
    if (blockIdx.x == 0 && (threadIdx.x >> 4) == 0) {
        for (int e = nquads * 4; e < E; e++) {
            const int s = __ldg(src_idx + e);
            const int d = __ldg(dst_idx + e);
            const uint2 w = __ldg(reinterpret_cast<const uint2*>(g_nu + (long long)s * D) + lane);
            const uint2 z = __ldg(reinterpret_cast<const uint2*>(g_ni + (long long)d * D) + lane);
            float c = dot4h(w, z);
            #pragma unroll
            for (int o = 8; o > 0; o >>= 1) c += __shfl_xor_sync(0xFFFFFFFFu, c, o);
            if (lane == 0) out[e] = c;
        }
    }
}

extern "C" void kernel_launch(void* const* d_in, const int* in_sizes, int n_in,
                              void* d_out, int out_size)
{
    const float* h_user = (const float*)d_in[0];
    const float* h_item = (const float*)d_in[1];
    const int*   src    = (const int*)d_in[2];
    const int*   dst    = (const int*)d_in[3];
    float*       out    = (float*)d_out;

    const int N_U = in_sizes[0] / D;
    const int N_I = in_sizes[1] / D;
    const int E   = in_sizes[2];
    const int N_T = N_U + N_I;

    {
        const int pairs = (N_T + 1) / 2;
        const long long t = (long long)pairs * 8;
        normalize_fused_kernel<<<(int)((t + THREADS - 1) / THREADS), THREADS>>>(
            h_user, h_item, N_U, N_T);
    }
    cosine_gather_kernel<<<GATHER_BLOCKS, THREADS>>>(src, dst, out, E);
}

// round 12
// speedup vs baseline: 1.2246x; 1.2246x over previous
#include <cuda_runtime.h>
#include <cuda_fp16.h>
#include <cstdint>

// CosinePrediction: cos[e] = <u[src[e]], v[dst[e]]> / (||u||*||v||)
// Phase 1 (single fused launch): L2-normalize ALL rows of both tensors,
//   store fp16 rows (128 B/row) in scratch.
// Phase 2: PERSISTENT gather, R8 shape (the measured optimum): 8 lanes per
//   edge-quad, uint4 loads (1 wavefront/row), index prefetch one iteration
//   ahead, depth-2 fp16 dot accumulation. This round: 5-blocks/SM reg budget
//   + 32-bit byte-offset addressing (row offsets fit 32 bits).

static constexpr int D = 64;
static constexpr int ROW_BYTES = D * 2;       // 128 B per fp16 row
static constexpr int MAX_ROWS = 100000;       // N_U = N_I = 100000 (fixed problem shape)
static constexpr int THREADS = 256;
static constexpr int GATHER_BLOCKS = 740;     // 5 blocks/SM * 148 SMs, persistent

// fp16 normalized rows (25.6 MB total scratch)
__device__ __half g_nu[(size_t)MAX_ROWS * D];
__device__ __half g_ni[(size_t)MAX_ROWS * D];

// ---------------- Phase 1: fused normalize + fp16 convert ----------------
__device__ __forceinline__ void norm_store(
    const float4 a, const float4 b, float rn, __half* __restrict__ drow, int lane)
{
    __half2 h[4];
    h[0] = __floats2half2_rn(a.x * rn, a.y * rn);
    h[1] = __floats2half2_rn(a.z * rn, a.w * rn);
    h[2] = __floats2half2_rn(b.x * rn, b.y * rn);
    h[3] = __floats2half2_rn(b.z * rn, b.w * rn);
    *reinterpret_cast<uint2*>(drow + 4 * lane)      = *reinterpret_cast<uint2*>(&h[0]);
    *reinterpret_cast<uint2*>(drow + 32 + 4 * lane) = *reinterpret_cast<uint2*>(&h[2]);
}

__global__ __launch_bounds__(THREADS) void normalize_fused_kernel(
    const float* __restrict__ h_user,
    const float* __restrict__ h_item,
    int n_user, int n_total)
{
    const int gid  = blockIdx.x * THREADS + threadIdx.x;
    const int p    = gid >> 3;           // row-pair index
    const int lane = gid & 7;
    const int r0   = p * 2;
    if (r0 >= n_total) return;
    const int r1 = r0 + 1;

    const float* src0 = (r0 < n_user) ? (h_user + (long long)r0 * D)
                                      : (h_item + (long long)(r0 - n_user) * D);
    __half* dst0 = (r0 < n_user) ? (g_nu + (long long)r0 * D)
                                 : (g_ni + (long long)(r0 - n_user) * D);

    const bool have1 = r1 < n_total;
    const float* src1 = src0;
    __half* dst1 = dst0;
    if (have1) {
        src1 = (r1 < n_user) ? (h_user + (long long)r1 * D)
                             : (h_item + (long long)(r1 - n_user) * D);
        dst1 = (r1 < n_user) ? (g_nu + (long long)r1 * D)
                             : (g_ni + (long long)(r1 - n_user) * D);
    }

    const float4 a0 = __ldg(reinterpret_cast<const float4*>(src0) + lane);
    const float4 b0 = __ldg(reinterpret_cast<const float4*>(src0) + lane + 8);
    const float4 a1 = __ldg(reinterpret_cast<const float4*>(src1) + lane);
    const float4 b1 = __ldg(reinterpret_cast<const float4*>(src1) + lane + 8);

    float n0 = a0.x * a0.x;
    n0 = fmaf(a0.y, a0.y, n0); n0 = fmaf(a0.z, a0.z, n0); n0 = fmaf(a0.w, a0.w, n0);
    n0 = fmaf(b0.x, b0.x, n0); n0 = fmaf(b0.y, b0.y, n0);
    n0 = fmaf(b0.z, b0.z, n0); n0 = fmaf(b0.w, b0.w, n0);

    float n1 = a1.x * a1.x;
    n1 = fmaf(a1.y, a1.y, n1); n1 = fmaf(a1.z, a1.z, n1); n1 = fmaf(a1.w, a1.w, n1);
    n1 = fmaf(b1.x, b1.x, n1); n1 = fmaf(b1.y, b1.y, n1);
    n1 = fmaf(b1.z, b1.z, n1); n1 = fmaf(b1.w, b1.w, n1);

    #pragma unroll
    for (int o = 4; o > 0; o >>= 1) {
        n0 += __shfl_xor_sync(0xFFFFFFFFu, n0, o);
        n1 += __shfl_xor_sync(0xFFFFFFFFu, n1, o);
    }

    norm_store(a0, b0, rsqrtf(n0), dst0, lane);
    if (have1) norm_store(a1, b1, rsqrtf(n1), dst1, lane);
}

// ---------------- Phase 2: persistent edge gather + dot ----------------
// Depth-2 fp16 accumulation: each HFMA2 slot sums exactly 2 products
// (one via HMUL2, one fused), then converts to fp32.
__device__ __forceinline__ float dot8h(uint4 w, uint4 z)
{
    const __half2* wh = reinterpret_cast<const __half2*>(&w);
    const __half2* zh = reinterpret_cast<const __half2*>(&z);
    const __half2 p01 = __hfma2(wh[0], zh[0], __hmul2(wh[1], zh[1]));
    const __half2 p23 = __hfma2(wh[2], zh[2], __hmul2(wh[3], zh[3]));
    const float2 f01 = __half22float2(p01);
    const float2 f23 = __half22float2(p23);
    return (f01.x + f01.y) + (f23.x + f23.y);
}

// 32-bit byte-offset gather: idx*128 + lane*16 fits comfortably in 32 bits.
__device__ __forceinline__ uint4 row_ld(const char* __restrict__ base, int idx, unsigned lane_off)
{
    return __ldg(reinterpret_cast<const uint4*>(base + ((unsigned)idx * (unsigned)ROW_BYTES + lane_off)));
}

__global__ __launch_bounds__(THREADS, 5) void cosine_gather_kernel(
    const int* __restrict__ src_idx,
    const int* __restrict__ dst_idx,
    float* __restrict__ out,
    int E)
{
    const int gid     = blockIdx.x * THREADS + threadIdx.x;
    const unsigned lo = ((unsigned)gid & 7u) * 16u;        // lane byte offset in row
    const int gstride = (GATHER_BLOCKS * THREADS) >> 3;    // quads per sweep
    const int nquads  = E >> 2;                            // full quads

    const char* __restrict__ bu = reinterpret_cast<const char*>(g_nu);
    const char* __restrict__ bi = reinterpret_cast<const char*>(g_ni);

    int g = gid >> 3;
    if (g < nquads) {
        // Prime the pipeline: indices for the first quad.
        int4 s4 = __ldg(reinterpret_cast<const int4*>(src_idx) + g);
        int4 d4 = __ldg(reinterpret_cast<const int4*>(dst_idx) + g);

        while (true) {
            const int gn = g + gstride;

            // 8 independent 16B gathers — indices already resident.
            const uint4 w0 = row_ld(bu, s4.x, lo);
            const uint4 z0 = row_ld(bi, d4.x, lo);
            const uint4 w1 = row_ld(bu, s4.y, lo);
            const uint4 z1 = row_ld(bi, d4.y, lo);
            const uint4 w2 = row_ld(bu, s4.z, lo);
            const uint4 z2 = row_ld(bi, d4.z, lo);
            const uint4 w3 = row_ld(bu, s4.w, lo);
            const uint4 z3 = row_ld(bi, d4.w, lo);

            // Prefetch next quad's indices while rows are in flight.
            const bool more = gn < nquads;
            if (more) {
                s4 = __ldg(reinterpret_cast<const int4*>(src_idx) + gn);
                d4 = __ldg(reinterpret_cast<const int4*>(dst_idx) + gn);
            }

            float c0 = dot8h(w0, z0);
            float c1 = dot8h(w1, z1);
            float c2 = dot8h(w2, z2);
            float c3 = dot8h(w3, z3);

            #pragma unroll
            for (int o = 4; o > 0; o >>= 1) {
                c0 += __shfl_xor_sync(0xFFFFFFFFu, c0, o);
                c1 += __shfl_xor_sync(0xFFFFFFFFu, c1, o);
                c2 += __shfl_xor_sync(0xFFFFFFFFu, c2, o);
                c3 += __shfl_xor_sync(0xFFFFFFFFu, c3, o);
            }

            if (lo == 0) {
                float4 r; r.x = c0; r.y = c1; r.z = c2; r.w = c3;
                *reinterpret_cast<float4*>(out + g * 4) = r;   // single STG.128
            }

            if (!more) break;
            g = gn;
        }
    }

    // Tail edges (E % 4), handled by the first lane-group of block 0.
    if (blockIdx.x == 0 && (threadIdx.x >> 3) == 0) {
        for (int e = nquads * 4; e < E; e++) {
            const int s = __ldg(src_idx + e);
            const int d = __ldg(dst_idx + e);
            const uint4 w = row_ld(bu, s, lo);
            const uint4 z = row_ld(bi, d, lo);
            float c = dot8h(w, z);
            #pragma unroll
            for (int o = 4; o > 0; o >>= 1) c += __shfl_xor_sync(0xFFFFFFFFu, c, o);
            if (lo == 0) out[e] = c;
        }
    }
}

extern "C" void kernel_launch(void* const* d_in, const int* in_sizes, int n_in,
                              void* d_out, int out_size)
{
    const float* h_user = (const float*)d_in[0];
    const float* h_item = (const float*)d_in[1];
    const int*   src    = (const int*)d_in[2];
    const int*   dst    = (const int*)d_in[3];
    float*       out    = (float*)d_out;

    const int N_U = in_sizes[0] / D;
    const int N_I = in_sizes[1] / D;
    const int E   = in_sizes[2];
    const int N_T = N_U + N_I;

    {
        const int pairs = (N_T + 1) / 2;
        const long long t = (long long)pairs * 8;
        normalize_fused_kernel<<<(int)((t + THREADS - 1) / THREADS), THREADS>>>(
            h_user, h_item, N_U, N_T);
    }
    cosine_gather_kernel<<<GATHER_BLOCKS, THREADS>>>(src, dst, out, E);
}